// round 4
// baseline (speedup 1.0000x reference)
#include <cuda_runtime.h>
#include <cstdint>
#include <cstddef>

#define NN 3072
#define FB 512     // working block width (256 complex -> 512 real cols)
#define FOUT 256
#define FIN 512
#define NPACK 1280 // [wr1|wi1 | wr0|wi0 | w0]

// ---------------- scratch (device globals) -------------------------------------
__device__ __align__(128) float g_P[NN * NPACK];    // packed projections
__device__ __align__(128) float g_WALL[FIN * NPACK];
__device__ __align__(128) float g_Q[NN * FB];
__device__ __align__(128) float g_Y[NN * FB];
__device__ __align__(128) float g_XJ[NN * FB];
__device__ __align__(128) float g_G[3 * NN * FB];   // split-K partials
__device__ __align__(128) float g_dr[NN];
__device__ __align__(128) float g_di[NN];

// ---------------- tf32 helpers ------------------------------------------------
__device__ __forceinline__ uint32_t f2tf(float x) {
    uint32_t u;
    asm("cvt.rna.tf32.f32 %0, %1;" : "=r"(u) : "f"(x));
    return u;
}

__device__ __forceinline__ void mma8(float c[4],
                                     uint32_t a0, uint32_t a1, uint32_t a2, uint32_t a3,
                                     uint32_t b0, uint32_t b1) {
    asm volatile(
        "mma.sync.aligned.m16n8k8.row.col.f32.tf32.tf32.f32 "
        "{%0,%1,%2,%3}, {%4,%5,%6,%7}, {%8,%9}, {%0,%1,%2,%3};"
        : "+f"(c[0]), "+f"(c[1]), "+f"(c[2]), "+f"(c[3])
        : "r"(a0), "r"(a1), "r"(a2), "r"(a3), "r"(b0), "r"(b1));
}

// ================= BIG GEMM: 128x128 CTA, 128 threads, warp tile 64x64 =========
// C[z] = A(:, z*Ks:(z+1)*Ks) @ B(z*Ks:..., :), row-major, tf32 (pre-rounded smem).
// A smem permuted fragment-ready: frag = one LDS.128.
__global__ void __launch_bounds__(128, 2)
gemm_big(const float* __restrict__ A, int lda,
         const float* __restrict__ B, int ldb,
         float* __restrict__ C, int ldc,
         int Kslice, size_t cPlane) {
    constexpr int BK = 16, LDB = 136;
    constexpr int AT = 264, AK8 = 1056, AST = 2112;
    __shared__ float Asp[2 * AST];
    __shared__ float Bs[2][BK][LDB];

    const int tid  = threadIdx.x;
    const int lane = tid & 31;
    const int warp = tid >> 5;          // 0..3
    const int wm   = (warp >> 1) * 64;  // warp m offset
    const int wn   = (warp & 1) * 64;   // warp n offset
    const int wri  = warp >> 1;         // warp m index (0..1)
    const int g    = lane >> 2;
    const int t    = lane & 3;
    const int bM   = blockIdx.y * 128;
    const int bN   = blockIdx.x * 128;
    const int kbase = blockIdx.z * Kslice;

    // A store mapping: thread owns row am = tid, 4 float4 along k
    const int am   = tid;
    const int mg   = (am & 7) | ((am >> 4) << 3);
    const int msel = (am >> 3) & 1;
    int aoff[4];
#pragma unroll
    for (int c = 0; c < 4; c++)
        aoff[c] = (c >> 1) * AK8 + mg * 4 + (c & 1) * 2 + msel;

    // B store mapping: rows bk+4r, cols bn4
    const int bk  = tid >> 5;
    const int bn4 = (tid & 31) * 4;

    const float* Ag = A + (size_t)(bM + am) * lda + kbase;
    const float* Bg = B + (size_t)(kbase + bk) * ldb + bN + bn4;

    float acc[4][8][4];
#pragma unroll
    for (int i = 0; i < 4; i++)
#pragma unroll
        for (int j = 0; j < 8; j++)
#pragma unroll
            for (int k = 0; k < 4; k++) acc[i][j][k] = 0.f;

    const int nT = Kslice / BK;
    float4 ra[4], rb[4];

    auto cvt = [](float v) -> float {
        uint32_t u;
        asm("cvt.rna.tf32.f32 %0, %1;" : "=r"(u) : "f"(v));
        return __uint_as_float(u);
    };

    auto storeTile = [&](int buf) {
        float* Ab = Asp + buf * AST;
#pragma unroll
        for (int c = 0; c < 4; c++) {
            Ab[aoff[c] + 0 * AT] = cvt(ra[c].x);
            Ab[aoff[c] + 1 * AT] = cvt(ra[c].y);
            Ab[aoff[c] + 2 * AT] = cvt(ra[c].z);
            Ab[aoff[c] + 3 * AT] = cvt(ra[c].w);
        }
#pragma unroll
        for (int r = 0; r < 4; r++) {
            Bs[buf][bk + 4 * r][bn4 + 0] = cvt(rb[r].x);
            Bs[buf][bk + 4 * r][bn4 + 1] = cvt(rb[r].y);
            Bs[buf][bk + 4 * r][bn4 + 2] = cvt(rb[r].z);
            Bs[buf][bk + 4 * r][bn4 + 3] = cvt(rb[r].w);
        }
    };

    // prologue
#pragma unroll
    for (int c = 0; c < 4; c++) ra[c] = *(const float4*)(Ag + c * 4);
#pragma unroll
    for (int r = 0; r < 4; r++) rb[r] = *(const float4*)(Bg + (size_t)(4 * r) * ldb);
    storeTile(0);
    __syncthreads();

    for (int kt = 0; kt < nT; kt++) {
        const int buf = kt & 1;
        if (kt + 1 < nT) {
            const float* Ap = Ag + (size_t)(kt + 1) * BK;
            const float* Bp = Bg + (size_t)(kt + 1) * BK * ldb;
#pragma unroll
            for (int c = 0; c < 4; c++) ra[c] = *(const float4*)(Ap + c * 4);
#pragma unroll
            for (int r = 0; r < 4; r++) rb[r] = *(const float4*)(Bp + (size_t)(4 * r) * ldb);
        }
        const float* Ab = Asp + buf * AST + t * AT;
#pragma unroll
        for (int ks = 0; ks < 2; ks++) {
            const int kb = ks * 8;
            float4 afv[4];
            float bf[8][2];
#pragma unroll
            for (int mt = 0; mt < 4; mt++)
                afv[mt] = *(const float4*)(Ab + ks * AK8 + ((wri * 4 + mt) * 8 + g) * 4);
#pragma unroll
            for (int nt = 0; nt < 8; nt++) {
                const int n0 = wn + nt * 8 + g;
                bf[nt][0] = Bs[buf][kb + t][n0];
                bf[nt][1] = Bs[buf][kb + t + 4][n0];
            }
#pragma unroll
            for (int mt = 0; mt < 4; mt++)
#pragma unroll
                for (int nt = 0; nt < 8; nt++)
                    mma8(acc[mt][nt],
                         __float_as_uint(afv[mt].x), __float_as_uint(afv[mt].y),
                         __float_as_uint(afv[mt].z), __float_as_uint(afv[mt].w),
                         __float_as_uint(bf[nt][0]), __float_as_uint(bf[nt][1]));
        }
        if (kt + 1 < nT) storeTile(buf ^ 1);
        __syncthreads();
    }

    float* Ct = C + blockIdx.z * cPlane;
#pragma unroll
    for (int mt = 0; mt < 4; mt++) {
        const int row = bM + wm + mt * 16 + g;
#pragma unroll
        for (int nt = 0; nt < 8; nt++) {
            const int col = bN + wn + nt * 8 + 2 * t;
            float* p = Ct + (size_t)row * ldc + col;
            p[0]                   = acc[mt][nt][0];
            p[1]                   = acc[mt][nt][1];
            p[(size_t)8 * ldc]     = acc[mt][nt][2];
            p[(size_t)8 * ldc + 1] = acc[mt][nt][3];
        }
    }
}

// ================= SMALL GEMM (fp32-accurate split tf32), 256 thr, 128x128 =====
__global__ void __launch_bounds__(256)
gemm_split(const float* __restrict__ A, int lda,
           const float* __restrict__ B, int ldb,
           float* __restrict__ C, int ldc, int K) {
    constexpr int BK = 16, LDB = 136;
    constexpr int AT = 264, AK8 = 1056, AST = 2112;
    __shared__ float Asp[2 * AST];
    __shared__ float Bs[2][BK][LDB];

    const int tid  = threadIdx.x;
    const int lane = tid & 31;
    const int warp = tid >> 5;
    const int wrow = warp >> 2;
    const int wcol = warp & 3;
    const int g    = lane >> 2;
    const int t    = lane & 3;
    const int bM   = blockIdx.y * 128;
    const int bN   = blockIdx.x * 128;

    const int am   = tid >> 2;
    const int ac   = tid & 3;
    const int ak4  = ac * 4;
    const int mg0  = (am & 7) | ((am >> 4) << 3);
    const int msel = (am >> 3) & 1;
    const int aoff0 = (ac >> 1) * AK8 + mg0 * 4 + (ac & 1) * 2 + msel;
    const int aoff1 = aoff0 + 32 * 4;

    const int bk  = tid >> 5;
    const int bn4 = (tid & 31) * 4;

    const float* Ag = A + (size_t)(bM + am) * lda + ak4;
    const float* Bg = B + (size_t)bk * ldb + bN + bn4;
    const size_t Astride = (size_t)64 * lda;
    const size_t Bstride = (size_t)8 * ldb;

    float acc[4][4][4];
#pragma unroll
    for (int i = 0; i < 4; i++)
#pragma unroll
        for (int j = 0; j < 4; j++)
#pragma unroll
            for (int k = 0; k < 4; k++) acc[i][j][k] = 0.f;

    const int nT = K / BK;
    float4 ra0, ra1, rb0, rb1;

    auto storeTile = [&](int buf, const float4& a0v, const float4& a1v,
                         const float4& b0v, const float4& b1v) {
        float* Ab = Asp + buf * AST;
        Ab[aoff0 + 0 * AT] = a0v.x; Ab[aoff0 + 1 * AT] = a0v.y;
        Ab[aoff0 + 2 * AT] = a0v.z; Ab[aoff0 + 3 * AT] = a0v.w;
        Ab[aoff1 + 0 * AT] = a1v.x; Ab[aoff1 + 1 * AT] = a1v.y;
        Ab[aoff1 + 2 * AT] = a1v.z; Ab[aoff1 + 3 * AT] = a1v.w;
        Bs[buf][bk][bn4 + 0] = b0v.x; Bs[buf][bk][bn4 + 1] = b0v.y;
        Bs[buf][bk][bn4 + 2] = b0v.z; Bs[buf][bk][bn4 + 3] = b0v.w;
        Bs[buf][bk + 8][bn4 + 0] = b1v.x; Bs[buf][bk + 8][bn4 + 1] = b1v.y;
        Bs[buf][bk + 8][bn4 + 2] = b1v.z; Bs[buf][bk + 8][bn4 + 3] = b1v.w;
    };

    ra0 = *(const float4*)(Ag);
    ra1 = *(const float4*)(Ag + Astride);
    rb0 = *(const float4*)(Bg);
    rb1 = *(const float4*)(Bg + Bstride);
    storeTile(0, ra0, ra1, rb0, rb1);
    __syncthreads();

    for (int kt = 0; kt < nT; kt++) {
        const int buf = kt & 1;
        if (kt + 1 < nT) {
            const float* Ap = Ag + (size_t)(kt + 1) * BK;
            const float* Bp = Bg + (size_t)(kt + 1) * BK * ldb;
            ra0 = *(const float4*)(Ap);
            ra1 = *(const float4*)(Ap + Astride);
            rb0 = *(const float4*)(Bp);
            rb1 = *(const float4*)(Bp + Bstride);
        }
        const float* Ab = Asp + buf * AST + t * AT;
#pragma unroll
        for (int ks = 0; ks < 2; ks++) {
            const int kb = ks * 8;
            float4 afv[4];
            float bf[4][2];
#pragma unroll
            for (int mt = 0; mt < 4; mt++)
                afv[mt] = *(const float4*)(Ab + ks * AK8 + ((wrow * 4 + mt) * 8 + g) * 4);
#pragma unroll
            for (int nt = 0; nt < 4; nt++) {
                const int n0 = wcol * 32 + nt * 8 + g;
                bf[nt][0] = Bs[buf][kb + t][n0];
                bf[nt][1] = Bs[buf][kb + t + 4][n0];
            }
            uint32_t ah[4][4], al[4][4], bh[4][2], bl[4][2];
#pragma unroll
            for (int mt = 0; mt < 4; mt++) {
                const float a4[4] = {afv[mt].x, afv[mt].y, afv[mt].z, afv[mt].w};
#pragma unroll
                for (int i = 0; i < 4; i++) {
                    uint32_t hb = f2tf(a4[i]);
                    ah[mt][i] = hb;
                    al[mt][i] = f2tf(a4[i] - __uint_as_float(hb));
                }
            }
#pragma unroll
            for (int nt = 0; nt < 4; nt++)
#pragma unroll
                for (int i = 0; i < 2; i++) {
                    uint32_t hb = f2tf(bf[nt][i]);
                    bh[nt][i] = hb;
                    bl[nt][i] = f2tf(bf[nt][i] - __uint_as_float(hb));
                }
#pragma unroll
            for (int mt = 0; mt < 4; mt++)
#pragma unroll
                for (int nt = 0; nt < 4; nt++) {
                    mma8(acc[mt][nt], al[mt][0], al[mt][1], al[mt][2], al[mt][3],
                         bh[nt][0], bh[nt][1]);
                    mma8(acc[mt][nt], ah[mt][0], ah[mt][1], ah[mt][2], ah[mt][3],
                         bl[nt][0], bl[nt][1]);
                    mma8(acc[mt][nt], ah[mt][0], ah[mt][1], ah[mt][2], ah[mt][3],
                         bh[nt][0], bh[nt][1]);
                }
        }
        if (kt + 1 < nT) storeTile(buf ^ 1, ra0, ra1, rb0, rb1);
        __syncthreads();
    }

#pragma unroll
    for (int mt = 0; mt < 4; mt++) {
        const int row = bM + wrow * 64 + mt * 16 + g;
#pragma unroll
        for (int nt = 0; nt < 4; nt++) {
            const int col = bN + wcol * 32 + nt * 8 + 2 * t;
            float* p = C + (size_t)row * ldc + col;
            p[0]                   = acc[mt][nt][0];
            p[1]                   = acc[mt][nt][1];
            p[(size_t)8 * ldc]     = acc[mt][nt][2];
            p[(size_t)8 * ldc + 1] = acc[mt][nt][3];
        }
    }
}

// ---------------- elementwise kernels -------------------------------------------

__global__ void rowsum_kernel(const float* __restrict__ adj, const float* __restrict__ hp,
                              float* __restrict__ dr, float* __restrict__ di) {
    __shared__ float sh[256];
    const int row = blockIdx.x;
    const float* a = adj + (size_t)row * NN;
    float s = 0.f;
    for (int c = threadIdx.x; c < NN; c += 256) s += a[c];
    sh[threadIdx.x] = s;
    __syncthreads();
    for (int o = 128; o > 0; o >>= 1) {
        if (threadIdx.x < o) sh[threadIdx.x] += sh[threadIdx.x + o];
        __syncthreads();
    }
    if (threadIdx.x == 0) {
        const float h = *hp;
        const float sv = h * (1.0f - sh[0]);
        const float inv = 1.0f / (sv * sv + 1.0f);
        dr[row] = sv * inv;
        di[row] = -inv;
    }
}

// pack WALL = [ wr1|wi1 | wr0|wi0 | w0 ]  ([FIN, 1280])
__global__ void packW_kernel(const float* __restrict__ w0,
                             const float* __restrict__ wr, const float* __restrict__ wi) {
    const int i = blockIdx.x * blockDim.x + threadIdx.x;   // over FIN*NPACK
    const int r = i / NPACK;
    const int c = i % NPACK;
    float v;
    if (c < 256)        v = wr[(size_t)FIN * FOUT + r * FOUT + c];
    else if (c < 512)   v = wi[(size_t)FIN * FOUT + r * FOUT + (c - 256)];
    else if (c < 768)   v = wr[(size_t)r * FOUT + (c - 512)];
    else if (c < 1024)  v = wi[(size_t)r * FOUT + (c - 768)];
    else                v = w0[(size_t)r * FOUT + (c - 1024)];
    g_WALL[i] = v;
}

// xj = (hL - iI)@Qsrc ; Y = XJ = xj.  G holds 3 split-K partials of adj@Qsrc.
__global__ void xj_kernel(const float* __restrict__ hp,
                          const float* __restrict__ Qsrc, int ldq) {
    const int r = blockIdx.x;
    const int c = threadIdx.x;
    const size_t idx  = (size_t)r * FB + c;
    const size_t idxI = idx + 256;
    const float h = *hp;
    const size_t P = (size_t)NN * FB;
    const float GR = g_G[idx] + g_G[idx + P] + g_G[idx + 2 * P];
    const float GI = g_G[idxI] + g_G[idxI + P] + g_G[idxI + 2 * P];
    const float qr = Qsrc[(size_t)r * ldq + c];
    const float qi = Qsrc[(size_t)r * ldq + c + 256];
    const float xr = h * qr - h * GR + qi;
    const float xi = h * qi - h * GI - qr;
    g_XJ[idx] = xr; g_XJ[idxI] = xi;
    g_Y[idx]  = xr; g_Y[idxI]  = xi;
}

__global__ void jacobi_kernel(const float* __restrict__ hp,
                              const float* __restrict__ dr, const float* __restrict__ di) {
    const int r = blockIdx.x;
    const int c = threadIdx.x;
    const size_t idx  = (size_t)r * FB + c;
    const size_t idxI = idx + 256;
    const float h = *hp;
    const size_t P = (size_t)NN * FB;
    const float GR = g_G[idx] + g_G[idx + P] + g_G[idx + 2 * P];
    const float GI = g_G[idxI] + g_G[idxI + P] + g_G[idxI + 2 * P];
    const float yr = g_Y[idx], yi = g_Y[idxI];
    const float azr = h * yr - h * GR;
    const float azi = h * yi - h * GI;
    const float rr = g_XJ[idx]  - (azr - yi);
    const float ri = g_XJ[idxI] - (azi + yr);
    const float d_r = dr[r], d_i = di[r];
    g_Y[idx]  = yr + d_r * rr - d_i * ri;
    g_Y[idxI] = yi + d_r * ri + d_i * rr;
}

// Q = P1 + Y   (P1 = g_P[:, 512:1024])
__global__ void formQ_kernel() {
    const size_t i = (size_t)blockIdx.x * blockDim.x + threadIdx.x;
    const size_t r = i >> 9;
    const size_t c = i & 511;
    g_Q[i] = g_P[r * NPACK + 512 + c] + g_Y[i];
}

// out = relu(out0 + 2*Re(Y)) ; out0 = g_P[:, 1024:1280]
__global__ void relu_kernel(float* __restrict__ out) {
    const int i = blockIdx.x * blockDim.x + threadIdx.x;
    const size_t r = i >> 8;
    const size_t c = i & 255;
    const float v = g_P[r * NPACK + 1024 + c] + 2.f * g_Y[r * FB + c];
    out[i] = v > 0.f ? v : 0.f;
}

// ---------------- orchestration --------------------------------------------------
static void applyK(const float* adj, const float* hp, const float* dr, const float* di,
                   const float* Qsrc, int ldq, float* Y, float* G) {
    const dim3 blk(128);
    const dim3 gridBig(4, 24, 3);   // N=512/128, M=3072/128, splitK=3
    gemm_big<<<gridBig, blk>>>(adj, NN, Qsrc, ldq, G, FB, 1024, (size_t)NN * FB);
    xj_kernel<<<NN, 256>>>(hp, Qsrc, ldq);
    for (int it = 0; it < 3; it++) {
        gemm_big<<<gridBig, blk>>>(adj, NN, Y, FB, G, FB, 1024, (size_t)NN * FB);
        jacobi_kernel<<<NN, 256>>>(hp, dr, di);
    }
}

extern "C" void kernel_launch(void* const* d_in, const int* in_sizes, int n_in,
                              void* d_out, int out_size) {
    const float* x   = (const float*)d_in[0];
    const float* adj = (const float*)d_in[1];
    const float* hp  = (const float*)d_in[2];
    const float* w0  = (const float*)d_in[3];
    const float* wr  = (const float*)d_in[4];
    const float* wi  = (const float*)d_in[5];
    float* out = (float*)d_out;

    float *Pp, *WALL, *Q, *Y, *G, *dr, *di;
    cudaGetSymbolAddress((void**)&Pp, g_P);
    cudaGetSymbolAddress((void**)&WALL, g_WALL);
    cudaGetSymbolAddress((void**)&Q, g_Q);
    cudaGetSymbolAddress((void**)&Y, g_Y);
    cudaGetSymbolAddress((void**)&G, g_G);
    cudaGetSymbolAddress((void**)&dr, g_dr);
    cudaGetSymbolAddress((void**)&di, g_di);

    rowsum_kernel<<<NN, 256>>>(adj, hp, dr, di);
    packW_kernel<<<(FIN * NPACK) / 256, 256>>>(w0, wr, wi);

    // P = x @ WALL : [3072, 1280] = [P2 | P1 | out0]
    gemm_split<<<dim3(NPACK / 128, NN / 128), 256>>>(x, FIN, WALL, NPACK, Pp, NPACK, FIN);

    // Y = K @ P2   (P2 = P[:, 0:512], ld 1280)
    applyK(adj, hp, dr, di, Pp, NPACK, Y, G);

    // Q = P1 + Y
    formQ_kernel<<<(NN * FB) / 256, 256>>>();

    // Y = K @ Q  (= csum)
    applyK(adj, hp, dr, di, Q, FB, Y, G);

    // out = relu(out0 + 2*Re(csum))
    relu_kernel<<<(NN * FOUT) / 256, 256>>>(out);
}

// round 5
// speedup vs baseline: 1.5264x; 1.5264x over previous
#include <cuda_runtime.h>
#include <cstdint>
#include <cstddef>

#define NN 3072
#define FB 512     // working block width (256 complex -> 512 real cols)
#define FOUT 256
#define FIN 512
#define NPACK 1280 // [wr1|wi1 | wr0|wi0 | w0]

// ---------------- scratch (device globals) -------------------------------------
__device__ __align__(128) float g_P[NN * NPACK];    // packed projections
__device__ __align__(128) float g_WALL[FIN * NPACK];
__device__ __align__(128) float g_Q[NN * FB];
__device__ __align__(128) float g_Y[NN * FB];
__device__ __align__(128) float g_XJ[NN * FB];
__device__ __align__(128) float g_G[3 * NN * FB];   // split-K partials
__device__ __align__(128) float g_dr[NN];
__device__ __align__(128) float g_di[NN];

// ---------------- helpers -------------------------------------------------------
__device__ __forceinline__ uint32_t f2tf(float x) {
    uint32_t u;
    asm("cvt.rna.tf32.f32 %0, %1;" : "=r"(u) : "f"(x));
    return u;
}

__device__ __forceinline__ uint32_t packbf(float lo, float hi) {
    uint32_t d;
    asm("cvt.rn.bf16x2.f32 %0, %1, %2;" : "=r"(d) : "f"(hi), "f"(lo));
    return d;
}

__device__ __forceinline__ void mma8(float c[4],
                                     uint32_t a0, uint32_t a1, uint32_t a2, uint32_t a3,
                                     uint32_t b0, uint32_t b1) {
    asm volatile(
        "mma.sync.aligned.m16n8k8.row.col.f32.tf32.tf32.f32 "
        "{%0,%1,%2,%3}, {%4,%5,%6,%7}, {%8,%9}, {%0,%1,%2,%3};"
        : "+f"(c[0]), "+f"(c[1]), "+f"(c[2]), "+f"(c[3])
        : "r"(a0), "r"(a1), "r"(a2), "r"(a3), "r"(b0), "r"(b1));
}

__device__ __forceinline__ void mma16(float c[4],
                                      uint32_t a0, uint32_t a1, uint32_t a2, uint32_t a3,
                                      uint32_t b0, uint32_t b1) {
    asm volatile(
        "mma.sync.aligned.m16n8k16.row.col.f32.bf16.bf16.f32 "
        "{%0,%1,%2,%3}, {%4,%5,%6,%7}, {%8,%9}, {%0,%1,%2,%3};"
        : "+f"(c[0]), "+f"(c[1]), "+f"(c[2]), "+f"(c[3])
        : "r"(a0), "r"(a1), "r"(a2), "r"(a3), "r"(b0), "r"(b1));
}

// ================= BIG GEMM (bf16 m16n8k16): 128x128 CTA, 256 thr ==============
// C[z] = A(:, z*Ks:(z+1)*Ks) @ B(z*Ks:..., :), row-major fp32 in, fp32 out.
// Operands converted to bf16 at smem store. Warp tile 64x32 (2x4 warp grid).
// A smem: fragment-ready uint32[2][4(t)][64(mg)][4(reg)], t-stride 264, stage 1056.
//   frag for (warp, mt) = one LDS.128 per thread, conflict-free.
// B smem: bf16x2 pairs uint32[2][8(k2)][136], LDS.32 conflict-free.
__global__ void __launch_bounds__(256, 2)
gemm_big(const float* __restrict__ A, int lda,
         const float* __restrict__ B, int ldb,
         float* __restrict__ C, int ldc,
         int Kslice, size_t cPlane) {
    constexpr int BK = 16;
    constexpr int AT = 264, AST = 1056;   // uint32 units
    constexpr int LDBu = 136;
    __shared__ __align__(16) uint32_t Asp[2 * AST];
    __shared__ __align__(16) uint32_t Bs[2][8][LDBu];

    const int tid  = threadIdx.x;
    const int lane = tid & 31;
    const int warp = tid >> 5;
    const int wrow = warp >> 2;   // 0..1
    const int wcol = warp & 3;    // 0..3
    const int g    = lane >> 2;
    const int t    = lane & 3;
    const int bM   = blockIdx.y * 128;
    const int bN   = blockIdx.x * 128;
    const int kbase = blockIdx.z * Kslice;

    // A gmem->smem: thread owns row am (0..127), k-half ac*8
    const int am   = tid >> 1;
    const int ac   = tid & 1;
    const int mg   = (am & 7) | ((am >> 4) << 3);
    const int msel = (am >> 3) & 1;
    const int regb = ac * 2 + msel;       // a-reg index: khalf*2 + msel
    const int abase = mg * 4 + regb;      // + t'*AT

    // B gmem->smem: thread owns k2 = bkr (rows 2bkr,2bkr+1), cols bn4..bn4+3
    const int bkr = tid >> 5;
    const int bn4 = (tid & 31) * 4;

    const float* Ag = A + (size_t)(bM + am) * lda + kbase + ac * 8;
    const float* Bg = B + (size_t)(kbase + 2 * bkr) * ldb + bN + bn4;

    float acc[4][4][4];
#pragma unroll
    for (int i = 0; i < 4; i++)
#pragma unroll
        for (int j = 0; j < 4; j++)
#pragma unroll
            for (int k = 0; k < 4; k++) acc[i][j][k] = 0.f;

    const int nT = Kslice / BK;
    float4 fa0, fa1, fb0, fb1;

    auto storeTile = [&](int buf) {
        uint32_t* Ab = Asp + buf * AST + abase;
        Ab[0 * AT] = packbf(fa0.x, fa0.y);
        Ab[1 * AT] = packbf(fa0.z, fa0.w);
        Ab[2 * AT] = packbf(fa1.x, fa1.y);
        Ab[3 * AT] = packbf(fa1.z, fa1.w);
        uint32_t* Bb = &Bs[buf][bkr][bn4];
        Bb[0] = packbf(fb0.x, fb1.x);
        Bb[1] = packbf(fb0.y, fb1.y);
        Bb[2] = packbf(fb0.z, fb1.z);
        Bb[3] = packbf(fb0.w, fb1.w);
    };

    // prologue
    fa0 = *(const float4*)(Ag);
    fa1 = *(const float4*)(Ag + 4);
    fb0 = *(const float4*)(Bg);
    fb1 = *(const float4*)(Bg + ldb);
    storeTile(0);
    __syncthreads();

    for (int kt = 0; kt < nT; kt++) {
        const int buf = kt & 1;
        if (kt + 1 < nT) {
            const float* Ap = Ag + (size_t)(kt + 1) * BK;
            const float* Bp = Bg + (size_t)(kt + 1) * BK * ldb;
            fa0 = *(const float4*)(Ap);
            fa1 = *(const float4*)(Ap + 4);
            fb0 = *(const float4*)(Bp);
            fb1 = *(const float4*)(Bp + ldb);
        }
        const uint32_t* Ab = Asp + buf * AST + t * AT;
        uint4 afv[4];
        uint32_t bf[4][2];
#pragma unroll
        for (int mt = 0; mt < 4; mt++)
            afv[mt] = *(const uint4*)(Ab + ((wrow * 4 + mt) * 8 + g) * 4);
#pragma unroll
        for (int nt = 0; nt < 4; nt++) {
            const int n0 = wcol * 32 + nt * 8 + g;
            bf[nt][0] = Bs[buf][t][n0];
            bf[nt][1] = Bs[buf][t + 4][n0];
        }
#pragma unroll
        for (int mt = 0; mt < 4; mt++)
#pragma unroll
            for (int nt = 0; nt < 4; nt++)
                mma16(acc[mt][nt], afv[mt].x, afv[mt].y, afv[mt].z, afv[mt].w,
                      bf[nt][0], bf[nt][1]);
        if (kt + 1 < nT) storeTile(buf ^ 1);
        __syncthreads();
    }

    float* Ct = C + blockIdx.z * cPlane;
#pragma unroll
    for (int mt = 0; mt < 4; mt++) {
        const int row = bM + wrow * 64 + mt * 16 + g;
#pragma unroll
        for (int nt = 0; nt < 4; nt++) {
            const int col = bN + wcol * 32 + nt * 8 + 2 * t;
            float* p = Ct + (size_t)row * ldc + col;
            p[0]                   = acc[mt][nt][0];
            p[1]                   = acc[mt][nt][1];
            p[(size_t)8 * ldc]     = acc[mt][nt][2];
            p[(size_t)8 * ldc + 1] = acc[mt][nt][3];
        }
    }
}

// ================= SMALL GEMM (fp32-accurate split tf32), 256 thr, 128x128 =====
__global__ void __launch_bounds__(256)
gemm_split(const float* __restrict__ A, int lda,
           const float* __restrict__ B, int ldb,
           float* __restrict__ C, int ldc, int K) {
    constexpr int BK = 16, LDB = 136;
    constexpr int AT = 264, AK8 = 1056, AST = 2112;
    __shared__ float Asp[2 * AST];
    __shared__ float Bs[2][BK][LDB];

    const int tid  = threadIdx.x;
    const int lane = tid & 31;
    const int warp = tid >> 5;
    const int wrow = warp >> 2;
    const int wcol = warp & 3;
    const int g    = lane >> 2;
    const int t    = lane & 3;
    const int bM   = blockIdx.y * 128;
    const int bN   = blockIdx.x * 128;

    const int am   = tid >> 2;
    const int ac   = tid & 3;
    const int ak4  = ac * 4;
    const int mg0  = (am & 7) | ((am >> 4) << 3);
    const int msel = (am >> 3) & 1;
    const int aoff0 = (ac >> 1) * AK8 + mg0 * 4 + (ac & 1) * 2 + msel;
    const int aoff1 = aoff0 + 32 * 4;

    const int bk  = tid >> 5;
    const int bn4 = (tid & 31) * 4;

    const float* Ag = A + (size_t)(bM + am) * lda + ak4;
    const float* Bg = B + (size_t)bk * ldb + bN + bn4;
    const size_t Astride = (size_t)64 * lda;
    const size_t Bstride = (size_t)8 * ldb;

    float acc[4][4][4];
#pragma unroll
    for (int i = 0; i < 4; i++)
#pragma unroll
        for (int j = 0; j < 4; j++)
#pragma unroll
            for (int k = 0; k < 4; k++) acc[i][j][k] = 0.f;

    const int nT = K / BK;
    float4 ra0, ra1, rb0, rb1;

    auto storeTile = [&](int buf, const float4& a0v, const float4& a1v,
                         const float4& b0v, const float4& b1v) {
        float* Ab = Asp + buf * AST;
        Ab[aoff0 + 0 * AT] = a0v.x; Ab[aoff0 + 1 * AT] = a0v.y;
        Ab[aoff0 + 2 * AT] = a0v.z; Ab[aoff0 + 3 * AT] = a0v.w;
        Ab[aoff1 + 0 * AT] = a1v.x; Ab[aoff1 + 1 * AT] = a1v.y;
        Ab[aoff1 + 2 * AT] = a1v.z; Ab[aoff1 + 3 * AT] = a1v.w;
        Bs[buf][bk][bn4 + 0] = b0v.x; Bs[buf][bk][bn4 + 1] = b0v.y;
        Bs[buf][bk][bn4 + 2] = b0v.z; Bs[buf][bk][bn4 + 3] = b0v.w;
        Bs[buf][bk + 8][bn4 + 0] = b1v.x; Bs[buf][bk + 8][bn4 + 1] = b1v.y;
        Bs[buf][bk + 8][bn4 + 2] = b1v.z; Bs[buf][bk + 8][bn4 + 3] = b1v.w;
    };

    ra0 = *(const float4*)(Ag);
    ra1 = *(const float4*)(Ag + Astride);
    rb0 = *(const float4*)(Bg);
    rb1 = *(const float4*)(Bg + Bstride);
    storeTile(0, ra0, ra1, rb0, rb1);
    __syncthreads();

    for (int kt = 0; kt < nT; kt++) {
        const int buf = kt & 1;
        if (kt + 1 < nT) {
            const float* Ap = Ag + (size_t)(kt + 1) * BK;
            const float* Bp = Bg + (size_t)(kt + 1) * BK * ldb;
            ra0 = *(const float4*)(Ap);
            ra1 = *(const float4*)(Ap + Astride);
            rb0 = *(const float4*)(Bp);
            rb1 = *(const float4*)(Bp + Bstride);
        }
        const float* Ab = Asp + buf * AST + t * AT;
#pragma unroll
        for (int ks = 0; ks < 2; ks++) {
            float4 afv[4];
            float bfr[4][2];
            const int kb = ks * 8;
#pragma unroll
            for (int mt = 0; mt < 4; mt++)
                afv[mt] = *(const float4*)(Ab + ks * AK8 + ((wrow * 4 + mt) * 8 + g) * 4);
#pragma unroll
            for (int nt = 0; nt < 4; nt++) {
                const int n0 = wcol * 32 + nt * 8 + g;
                bfr[nt][0] = Bs[buf][kb + t][n0];
                bfr[nt][1] = Bs[buf][kb + t + 4][n0];
            }
            uint32_t ah[4][4], al[4][4], bh[4][2], bl[4][2];
#pragma unroll
            for (int mt = 0; mt < 4; mt++) {
                const float a4[4] = {afv[mt].x, afv[mt].y, afv[mt].z, afv[mt].w};
#pragma unroll
                for (int i = 0; i < 4; i++) {
                    uint32_t hb = f2tf(a4[i]);
                    ah[mt][i] = hb;
                    al[mt][i] = f2tf(a4[i] - __uint_as_float(hb));
                }
            }
#pragma unroll
            for (int nt = 0; nt < 4; nt++)
#pragma unroll
                for (int i = 0; i < 2; i++) {
                    uint32_t hb = f2tf(bfr[nt][i]);
                    bh[nt][i] = hb;
                    bl[nt][i] = f2tf(bfr[nt][i] - __uint_as_float(hb));
                }
#pragma unroll
            for (int mt = 0; mt < 4; mt++)
#pragma unroll
                for (int nt = 0; nt < 4; nt++) {
                    mma8(acc[mt][nt], al[mt][0], al[mt][1], al[mt][2], al[mt][3],
                         bh[nt][0], bh[nt][1]);
                    mma8(acc[mt][nt], ah[mt][0], ah[mt][1], ah[mt][2], ah[mt][3],
                         bl[nt][0], bl[nt][1]);
                    mma8(acc[mt][nt], ah[mt][0], ah[mt][1], ah[mt][2], ah[mt][3],
                         bh[nt][0], bh[nt][1]);
                }
        }
        if (kt + 1 < nT) storeTile(buf ^ 1, ra0, ra1, rb0, rb1);
        __syncthreads();
    }

#pragma unroll
    for (int mt = 0; mt < 4; mt++) {
        const int row = bM + wrow * 64 + mt * 16 + g;
#pragma unroll
        for (int nt = 0; nt < 4; nt++) {
            const int col = bN + wcol * 32 + nt * 8 + 2 * t;
            float* p = C + (size_t)row * ldc + col;
            p[0]                   = acc[mt][nt][0];
            p[1]                   = acc[mt][nt][1];
            p[(size_t)8 * ldc]     = acc[mt][nt][2];
            p[(size_t)8 * ldc + 1] = acc[mt][nt][3];
        }
    }
}

// ---------------- elementwise kernels -------------------------------------------

__global__ void rowsum_kernel(const float* __restrict__ adj, const float* __restrict__ hp,
                              float* __restrict__ dr, float* __restrict__ di) {
    __shared__ float sh[256];
    const int row = blockIdx.x;
    const float* a = adj + (size_t)row * NN;
    float s = 0.f;
    for (int c = threadIdx.x; c < NN; c += 256) s += a[c];
    sh[threadIdx.x] = s;
    __syncthreads();
    for (int o = 128; o > 0; o >>= 1) {
        if (threadIdx.x < o) sh[threadIdx.x] += sh[threadIdx.x + o];
        __syncthreads();
    }
    if (threadIdx.x == 0) {
        const float h = *hp;
        const float sv = h * (1.0f - sh[0]);
        const float inv = 1.0f / (sv * sv + 1.0f);
        dr[row] = sv * inv;
        di[row] = -inv;
    }
}

// pack WALL = [ wr1|wi1 | wr0|wi0 | w0 ]  ([FIN, 1280])
__global__ void packW_kernel(const float* __restrict__ w0,
                             const float* __restrict__ wr, const float* __restrict__ wi) {
    const int i = blockIdx.x * blockDim.x + threadIdx.x;
    const int r = i / NPACK;
    const int c = i % NPACK;
    float v;
    if (c < 256)        v = wr[(size_t)FIN * FOUT + r * FOUT + c];
    else if (c < 512)   v = wi[(size_t)FIN * FOUT + r * FOUT + (c - 256)];
    else if (c < 768)   v = wr[(size_t)r * FOUT + (c - 512)];
    else if (c < 1024)  v = wi[(size_t)r * FOUT + (c - 768)];
    else                v = w0[(size_t)r * FOUT + (c - 1024)];
    g_WALL[i] = v;
}

// xj = (hL - iI)@Qsrc ; Y = XJ = xj.  G holds 3 split-K partials of adj@Qsrc.
__global__ void xj_kernel(const float* __restrict__ hp,
                          const float* __restrict__ Qsrc, int ldq) {
    const int r = blockIdx.x;
    const int c = threadIdx.x;
    const size_t idx  = (size_t)r * FB + c;
    const size_t idxI = idx + 256;
    const float h = *hp;
    const size_t P = (size_t)NN * FB;
    const float GR = g_G[idx] + g_G[idx + P] + g_G[idx + 2 * P];
    const float GI = g_G[idxI] + g_G[idxI + P] + g_G[idxI + 2 * P];
    const float qr = Qsrc[(size_t)r * ldq + c];
    const float qi = Qsrc[(size_t)r * ldq + c + 256];
    const float xr = h * qr - h * GR + qi;
    const float xi = h * qi - h * GI - qr;
    g_XJ[idx] = xr; g_XJ[idxI] = xi;
    g_Y[idx]  = xr; g_Y[idxI]  = xi;
}

__global__ void jacobi_kernel(const float* __restrict__ hp,
                              const float* __restrict__ dr, const float* __restrict__ di) {
    const int r = blockIdx.x;
    const int c = threadIdx.x;
    const size_t idx  = (size_t)r * FB + c;
    const size_t idxI = idx + 256;
    const float h = *hp;
    const size_t P = (size_t)NN * FB;
    const float GR = g_G[idx] + g_G[idx + P] + g_G[idx + 2 * P];
    const float GI = g_G[idxI] + g_G[idxI + P] + g_G[idxI + 2 * P];
    const float yr = g_Y[idx], yi = g_Y[idxI];
    const float azr = h * yr - h * GR;
    const float azi = h * yi - h * GI;
    const float rr = g_XJ[idx]  - (azr - yi);
    const float ri = g_XJ[idxI] - (azi + yr);
    const float d_r = dr[r], d_i = di[r];
    g_Y[idx]  = yr + d_r * rr - d_i * ri;
    g_Y[idxI] = yi + d_r * ri + d_i * rr;
}

// Q = P1 + Y   (P1 = g_P[:, 512:1024])
__global__ void formQ_kernel() {
    const size_t i = (size_t)blockIdx.x * blockDim.x + threadIdx.x;
    const size_t r = i >> 9;
    const size_t c = i & 511;
    g_Q[i] = g_P[r * NPACK + 512 + c] + g_Y[i];
}

// out = relu(out0 + 2*Re(Y)) ; out0 = g_P[:, 1024:1280]
__global__ void relu_kernel(float* __restrict__ out) {
    const int i = blockIdx.x * blockDim.x + threadIdx.x;
    const size_t r = i >> 8;
    const size_t c = i & 255;
    const float v = g_P[r * NPACK + 1024 + c] + 2.f * g_Y[r * FB + c];
    out[i] = v > 0.f ? v : 0.f;
}

// ---------------- orchestration --------------------------------------------------
static void applyK(const float* adj, const float* hp, const float* dr, const float* di,
                   const float* Qsrc, int ldq, float* Y, float* G) {
    const dim3 blk(256);
    const dim3 gridBig(4, 24, 3);   // N=512/128, M=3072/128, splitK=3
    gemm_big<<<gridBig, blk>>>(adj, NN, Qsrc, ldq, G, FB, 1024, (size_t)NN * FB);
    xj_kernel<<<NN, 256>>>(hp, Qsrc, ldq);
    for (int it = 0; it < 3; it++) {
        gemm_big<<<gridBig, blk>>>(adj, NN, Y, FB, G, FB, 1024, (size_t)NN * FB);
        jacobi_kernel<<<NN, 256>>>(hp, dr, di);
    }
}

extern "C" void kernel_launch(void* const* d_in, const int* in_sizes, int n_in,
                              void* d_out, int out_size) {
    const float* x   = (const float*)d_in[0];
    const float* adj = (const float*)d_in[1];
    const float* hp  = (const float*)d_in[2];
    const float* w0  = (const float*)d_in[3];
    const float* wr  = (const float*)d_in[4];
    const float* wi  = (const float*)d_in[5];
    float* out = (float*)d_out;

    float *Pp, *WALL, *Q, *Y, *G, *dr, *di;
    cudaGetSymbolAddress((void**)&Pp, g_P);
    cudaGetSymbolAddress((void**)&WALL, g_WALL);
    cudaGetSymbolAddress((void**)&Q, g_Q);
    cudaGetSymbolAddress((void**)&Y, g_Y);
    cudaGetSymbolAddress((void**)&G, g_G);
    cudaGetSymbolAddress((void**)&dr, g_dr);
    cudaGetSymbolAddress((void**)&di, g_di);

    rowsum_kernel<<<NN, 256>>>(adj, hp, dr, di);
    packW_kernel<<<(FIN * NPACK) / 256, 256>>>(w0, wr, wi);

    // P = x @ WALL : [3072, 1280] = [P2 | P1 | out0]
    gemm_split<<<dim3(NPACK / 128, NN / 128), 256>>>(x, FIN, WALL, NPACK, Pp, NPACK, FIN);

    // Y = K @ P2   (P2 = P[:, 0:512], ld 1280)
    applyK(adj, hp, dr, di, Pp, NPACK, Y, G);

    // Q = P1 + Y
    formQ_kernel<<<(NN * FB) / 256, 256>>>();

    // Y = K @ Q  (= csum)
    applyK(adj, hp, dr, di, Q, FB, Y, G);

    // out = relu(out0 + 2*Re(csum))
    relu_kernel<<<(NN * FOUT) / 256, 256>>>(out);
}

// round 7
// speedup vs baseline: 1.8946x; 1.2412x over previous
#include <cuda_runtime.h>
#include <cstdint>
#include <cstddef>

#define NN 3072
#define FB 512     // working block width (256 complex -> 512 real cols)
#define FOUT 256
#define FIN 512
#define NPACK 1280 // [wr1|wi1 | wr0|wi0 | w0]

// ---------------- scratch (device globals) -------------------------------------
__device__ __align__(1024) uint32_t g_adjp[(size_t)NN * NN / 2]; // bf16 fragment-tiled adj
__device__ __align__(1024) uint32_t g_Bbf[(NN / 2) * FB];        // bf16x2 interleaved B operand
__device__ __align__(128) float g_P[NN * NPACK];                 // packed projections
__device__ __align__(128) float g_WALL[FIN * NPACK];
__device__ __align__(128) float g_Q[NN * FB];
__device__ __align__(128) float g_Y[NN * FB];
__device__ __align__(128) float g_XJ[NN * FB];
__device__ __align__(128) float g_G[3 * NN * FB];                // split-K partials
__device__ __align__(128) float g_dr[NN];
__device__ __align__(128) float g_di[NN];

// ---------------- helpers -------------------------------------------------------
__device__ __forceinline__ uint32_t f2tf(float x) {
    uint32_t u;
    asm("cvt.rna.tf32.f32 %0, %1;" : "=r"(u) : "f"(x));
    return u;
}
__device__ __forceinline__ uint32_t packbf(float lo, float hi) {
    uint32_t d;
    asm("cvt.rn.bf16x2.f32 %0, %1, %2;" : "=r"(d) : "f"(hi), "f"(lo));
    return d;
}
__device__ __forceinline__ uint32_t smem_u32(const void* p) {
    uint32_t a;
    asm("{ .reg .u64 t; cvta.to.shared.u64 t, %1; cvt.u32.u64 %0, t; }" : "=r"(a) : "l"(p));
    return a;
}
__device__ __forceinline__ void cpasync16(uint32_t dst, const void* src) {
    asm volatile("cp.async.cg.shared.global [%0], [%1], 16;" :: "r"(dst), "l"(src) : "memory");
}

__device__ __forceinline__ void mma8(float c[4],
                                     uint32_t a0, uint32_t a1, uint32_t a2, uint32_t a3,
                                     uint32_t b0, uint32_t b1) {
    asm volatile(
        "mma.sync.aligned.m16n8k8.row.col.f32.tf32.tf32.f32 "
        "{%0,%1,%2,%3}, {%4,%5,%6,%7}, {%8,%9}, {%0,%1,%2,%3};"
        : "+f"(c[0]), "+f"(c[1]), "+f"(c[2]), "+f"(c[3])
        : "r"(a0), "r"(a1), "r"(a2), "r"(a3), "r"(b0), "r"(b1));
}
__device__ __forceinline__ void mma16(float c[4],
                                      uint32_t a0, uint32_t a1, uint32_t a2, uint32_t a3,
                                      uint32_t b0, uint32_t b1) {
    asm volatile(
        "mma.sync.aligned.m16n8k16.row.col.f32.bf16.bf16.f32 "
        "{%0,%1,%2,%3}, {%4,%5,%6,%7}, {%8,%9}, {%0,%1,%2,%3};"
        : "+f"(c[0]), "+f"(c[1]), "+f"(c[2]), "+f"(c[3])
        : "r"(a0), "r"(a1), "r"(a2), "r"(a3), "r"(b0), "r"(b1));
}

// ================= BIG GEMM: bf16-resident, cp.async 3-stage, BK=32 =============
// C[z][m][n] = sum_{k in slice z} adj[m][k] * Ybf[k][n]   (fp32 out, 128x128 CTA)
// A = g_adjp: fragment-ready tiles [mt:24][kt16:192] of 1024 uint32:
//   tile[t:4][mg:64][reg:4] ; smem copy adds pad: t-stride 264 uint32.
// B = g_Bbf: [pair-row 1536][feature 512] uint32 (k even/odd in lo/hi bf16).
__global__ void __launch_bounds__(256, 2)
gemm_big(const uint32_t* __restrict__ Ap, const uint32_t* __restrict__ Bbf,
         float* __restrict__ C, size_t cPlane) {
    // stage: A 2112 u32 (2 tiles, padded) + B 16x136 u32 = 4288 u32 = 17152 B; x3
    extern __shared__ __align__(16) uint32_t sm[];
    const uint32_t smb = smem_u32(sm);

    const int tid  = threadIdx.x;
    const int lane = tid & 31;
    const int warp = tid >> 5;
    const int wrow = warp >> 2;     // 0..1
    const int wcol = warp & 3;      // 0..3
    const int g    = lane >> 2;
    const int t    = lane & 3;
    const int bMt  = blockIdx.y;    // m tile (128 rows)
    const int bN   = blockIdx.x * 128;  // feature col base
    const int kt0  = blockIdx.z * 64;   // k16-tile base (splitK)

    float acc[4][4][4];
#pragma unroll
    for (int i = 0; i < 4; i++)
#pragma unroll
        for (int j = 0; j < 4; j++)
#pragma unroll
            for (int k = 0; k < 4; k++) acc[i][j][k] = 0.f;

    auto issueStage = [&](int st, int s) {
        const uint32_t stb = smb + st * 17152;
        const int kt16 = kt0 + s * 2;
        const uint32_t* asrc = Ap + ((size_t)bMt * 192 + kt16) * 1024;
#pragma unroll
        for (int i = 0; i < 2; i++) {
            const int c = tid + i * 256;            // 0..511
            const int j = c >> 8, w = c & 255;
            const int tt = w >> 6, mg = w & 63;
            cpasync16(stb + (uint32_t)(j * 1056 + tt * 264 + mg * 4) * 4, asrc + c * 4);
        }
        const uint32_t* bsrc = Bbf + ((size_t)kt16 * 8) * FB + bN;
#pragma unroll
        for (int i = 0; i < 2; i++) {
            const int c = tid + i * 256;
            const int row = c >> 5, c4 = (c & 31) * 4;
            cpasync16(stb + 8448 + (uint32_t)(row * 136 + c4) * 4,
                      bsrc + (size_t)row * FB + c4);
        }
        asm volatile("cp.async.commit_group;" ::: "memory");
    };

    const int nT = 32;   // 1024 k / 32
    issueStage(0, 0);
    issueStage(1, 1);

    for (int s = 0; s < nT; s++) {
        const int st = s % 3;
        if (s + 1 < nT) asm volatile("cp.async.wait_group 1;" ::: "memory");
        else            asm volatile("cp.async.wait_group 0;" ::: "memory");
        __syncthreads();
        if (s + 2 < nT) issueStage((s + 2) % 3, s + 2);

        const uint32_t* Abase = sm + st * 4288 + t * 264;
        const uint32_t* Bbase = sm + st * 4288 + 2112;
#pragma unroll
        for (int ks = 0; ks < 2; ks++) {
            uint4 afv[4];
            uint32_t bf[4][2];
#pragma unroll
            for (int mti = 0; mti < 4; mti++)
                afv[mti] = *(const uint4*)(Abase + ks * 1056 + ((wrow * 4 + mti) * 8 + g) * 4);
#pragma unroll
            for (int nt = 0; nt < 4; nt++) {
                const int n0 = wcol * 32 + nt * 8 + g;
                bf[nt][0] = Bbase[(ks * 8 + t) * 136 + n0];
                bf[nt][1] = Bbase[(ks * 8 + t + 4) * 136 + n0];
            }
#pragma unroll
            for (int mti = 0; mti < 4; mti++)
#pragma unroll
                for (int nt = 0; nt < 4; nt++)
                    mma16(acc[mti][nt], afv[mti].x, afv[mti].y, afv[mti].z, afv[mti].w,
                          bf[nt][0], bf[nt][1]);
        }
        __syncthreads();
    }

    float* Ct = C + blockIdx.z * cPlane;
#pragma unroll
    for (int mti = 0; mti < 4; mti++) {
        const int row = bMt * 128 + wrow * 64 + mti * 16 + g;
#pragma unroll
        for (int nt = 0; nt < 4; nt++) {
            const int col = bN + wcol * 32 + nt * 8 + 2 * t;
            float* p = Ct + (size_t)row * FB + col;
            p[0]                  = acc[mti][nt][0];
            p[1]                  = acc[mti][nt][1];
            p[(size_t)8 * FB]     = acc[mti][nt][2];
            p[(size_t)8 * FB + 1] = acc[mti][nt][3];
        }
    }
}

// ================= SMALL GEMM (fp32-accurate split tf32), as R5 ==================
__global__ void __launch_bounds__(256)
gemm_split(const float* __restrict__ A, int lda,
           const float* __restrict__ B, int ldb,
           float* __restrict__ C, int ldc, int K) {
    constexpr int BK = 16, LDB = 136;
    constexpr int AT = 264, AK8 = 1056, AST = 2112;
    __shared__ float Asp[2 * AST];
    __shared__ float Bs[2][BK][LDB];

    const int tid  = threadIdx.x;
    const int lane = tid & 31;
    const int warp = tid >> 5;
    const int wrow = warp >> 2;
    const int wcol = warp & 3;
    const int g    = lane >> 2;
    const int t    = lane & 3;
    const int bM   = blockIdx.y * 128;
    const int bN   = blockIdx.x * 128;

    const int am   = tid >> 2;
    const int ac   = tid & 3;
    const int ak4  = ac * 4;
    const int mg0  = (am & 7) | ((am >> 4) << 3);
    const int msel = (am >> 3) & 1;
    const int aoff0 = (ac >> 1) * AK8 + mg0 * 4 + (ac & 1) * 2 + msel;
    const int aoff1 = aoff0 + 32 * 4;

    const int bk  = tid >> 5;
    const int bn4 = (tid & 31) * 4;

    const float* Ag = A + (size_t)(bM + am) * lda + ak4;
    const float* Bg = B + (size_t)bk * ldb + bN + bn4;
    const size_t Astride = (size_t)64 * lda;
    const size_t Bstride = (size_t)8 * ldb;

    float acc[4][4][4];
#pragma unroll
    for (int i = 0; i < 4; i++)
#pragma unroll
        for (int j = 0; j < 4; j++)
#pragma unroll
            for (int k = 0; k < 4; k++) acc[i][j][k] = 0.f;

    const int nT = K / BK;
    float4 ra0, ra1, rb0, rb1;

    auto storeTile = [&](int buf, const float4& a0v, const float4& a1v,
                         const float4& b0v, const float4& b1v) {
        float* Ab = Asp + buf * AST;
        Ab[aoff0 + 0 * AT] = a0v.x; Ab[aoff0 + 1 * AT] = a0v.y;
        Ab[aoff0 + 2 * AT] = a0v.z; Ab[aoff0 + 3 * AT] = a0v.w;
        Ab[aoff1 + 0 * AT] = a1v.x; Ab[aoff1 + 1 * AT] = a1v.y;
        Ab[aoff1 + 2 * AT] = a1v.z; Ab[aoff1 + 3 * AT] = a1v.w;
        Bs[buf][bk][bn4 + 0] = b0v.x; Bs[buf][bk][bn4 + 1] = b0v.y;
        Bs[buf][bk][bn4 + 2] = b0v.z; Bs[buf][bk][bn4 + 3] = b0v.w;
        Bs[buf][bk + 8][bn4 + 0] = b1v.x; Bs[buf][bk + 8][bn4 + 1] = b1v.y;
        Bs[buf][bk + 8][bn4 + 2] = b1v.z; Bs[buf][bk + 8][bn4 + 3] = b1v.w;
    };

    ra0 = *(const float4*)(Ag);
    ra1 = *(const float4*)(Ag + Astride);
    rb0 = *(const float4*)(Bg);
    rb1 = *(const float4*)(Bg + Bstride);
    storeTile(0, ra0, ra1, rb0, rb1);
    __syncthreads();

    for (int kt = 0; kt < nT; kt++) {
        const int buf = kt & 1;
        if (kt + 1 < nT) {
            const float* Ap = Ag + (size_t)(kt + 1) * BK;
            const float* Bp = Bg + (size_t)(kt + 1) * BK * ldb;
            ra0 = *(const float4*)(Ap);
            ra1 = *(const float4*)(Ap + Astride);
            rb0 = *(const float4*)(Bp);
            rb1 = *(const float4*)(Bp + Bstride);
        }
        const float* Ab = Asp + buf * AST + t * AT;
#pragma unroll
        for (int ks = 0; ks < 2; ks++) {
            float4 afv[4];
            float bfr[4][2];
            const int kb = ks * 8;
#pragma unroll
            for (int mt = 0; mt < 4; mt++)
                afv[mt] = *(const float4*)(Ab + ks * AK8 + ((wrow * 4 + mt) * 8 + g) * 4);
#pragma unroll
            for (int nt = 0; nt < 4; nt++) {
                const int n0 = wcol * 32 + nt * 8 + g;
                bfr[nt][0] = Bs[buf][kb + t][n0];
                bfr[nt][1] = Bs[buf][kb + t + 4][n0];
            }
            uint32_t ah[4][4], al[4][4], bh[4][2], bl[4][2];
#pragma unroll
            for (int mt = 0; mt < 4; mt++) {
                const float a4[4] = {afv[mt].x, afv[mt].y, afv[mt].z, afv[mt].w};
#pragma unroll
                for (int i = 0; i < 4; i++) {
                    uint32_t hb = f2tf(a4[i]);
                    ah[mt][i] = hb;
                    al[mt][i] = f2tf(a4[i] - __uint_as_float(hb));
                }
            }
#pragma unroll
            for (int nt = 0; nt < 4; nt++)
#pragma unroll
                for (int i = 0; i < 2; i++) {
                    uint32_t hb = f2tf(bfr[nt][i]);
                    bh[nt][i] = hb;
                    bl[nt][i] = f2tf(bfr[nt][i] - __uint_as_float(hb));
                }
#pragma unroll
            for (int mt = 0; mt < 4; mt++)
#pragma unroll
                for (int nt = 0; nt < 4; nt++) {
                    mma8(acc[mt][nt], al[mt][0], al[mt][1], al[mt][2], al[mt][3],
                         bh[nt][0], bh[nt][1]);
                    mma8(acc[mt][nt], ah[mt][0], ah[mt][1], ah[mt][2], ah[mt][3],
                         bl[nt][0], bl[nt][1]);
                    mma8(acc[mt][nt], ah[mt][0], ah[mt][1], ah[mt][2], ah[mt][3],
                         bh[nt][0], bh[nt][1]);
                }
        }
        if (kt + 1 < nT) storeTile(buf ^ 1, ra0, ra1, rb0, rb1);
        __syncthreads();
    }

#pragma unroll
    for (int mt = 0; mt < 4; mt++) {
        const int row = bM + wrow * 64 + mt * 16 + g;
#pragma unroll
        for (int nt = 0; nt < 4; nt++) {
            const int col = bN + wcol * 32 + nt * 8 + 2 * t;
            float* p = C + (size_t)row * ldc + col;
            p[0]                   = acc[mt][nt][0];
            p[1]                   = acc[mt][nt][1];
            p[(size_t)8 * ldc]     = acc[mt][nt][2];
            p[(size_t)8 * ldc + 1] = acc[mt][nt][3];
        }
    }
}

// ---------------- pack / elementwise kernels -------------------------------------

// adj fp32 -> fragment-tiled bf16 (g_adjp). One block per (ktile, mtile).
__global__ void packAdj_kernel(const float* __restrict__ adj) {
    const int kt = blockIdx.x;          // 0..191
    const int mt = blockIdx.y;          // 0..23
    const int tp = threadIdx.x;         // 0..255
    const int mloc = tp >> 1, half = tp & 1;
    const int m = mt * 128 + mloc;
    const float* src = adj + (size_t)m * NN + kt * 16 + half * 8;
    const float4 v0 = *(const float4*)src;
    const float4 v1 = *(const float4*)(src + 4);
    const float v[8] = {v0.x, v0.y, v0.z, v0.w, v1.x, v1.y, v1.z, v1.w};
    const int mg   = (mloc & 7) | ((mloc >> 4) << 3);
    const int msel = (mloc >> 3) & 1;
    const int reg  = half * 2 + msel;
    uint32_t* dst = g_adjp + ((size_t)mt * 192 + kt) * 1024 + mg * 4 + reg;
#pragma unroll
    for (int tt = 0; tt < 4; tt++)
        dst[tt * 256] = packbf(v[2 * tt], v[2 * tt + 1]);
}

__global__ void rowsum_kernel(const float* __restrict__ adj, const float* __restrict__ hp,
                              float* __restrict__ dr, float* __restrict__ di) {
    __shared__ float sh[256];
    const int row = blockIdx.x;
    const float* a = adj + (size_t)row * NN;
    float s = 0.f;
    for (int c = threadIdx.x; c < NN; c += 256) s += a[c];
    sh[threadIdx.x] = s;
    __syncthreads();
    for (int o = 128; o > 0; o >>= 1) {
        if (threadIdx.x < o) sh[threadIdx.x] += sh[threadIdx.x + o];
        __syncthreads();
    }
    if (threadIdx.x == 0) {
        const float h = *hp;
        const float sv = h * (1.0f - sh[0]);
        const float inv = 1.0f / (sv * sv + 1.0f);
        dr[row] = sv * inv;
        di[row] = -inv;
    }
}

__global__ void packW_kernel(const float* __restrict__ w0,
                             const float* __restrict__ wr, const float* __restrict__ wi) {
    const int i = blockIdx.x * blockDim.x + threadIdx.x;
    const int r = i / NPACK;
    const int c = i % NPACK;
    float v;
    if (c < 256)        v = wr[(size_t)FIN * FOUT + r * FOUT + c];
    else if (c < 512)   v = wi[(size_t)FIN * FOUT + r * FOUT + (c - 256)];
    else if (c < 768)   v = wr[(size_t)r * FOUT + (c - 512)];
    else if (c < 1024)  v = wi[(size_t)r * FOUT + (c - 768)];
    else                v = w0[(size_t)r * FOUT + (c - 1024)];
    g_WALL[i] = v;
}

// Bbf[r][c] = bf16x2(P2[2r][c], P2[2r+1][c])  (P2 = g_P cols 0:512, ld NPACK)
__global__ void packP2_kernel() {
    const int i = blockIdx.x * 256 + threadIdx.x;   // over 1536*512
    const int r = i >> 9;
    const int c = i & 511;
    g_Bbf[(size_t)r * FB + c] = packbf(g_P[(size_t)(2 * r) * NPACK + c],
                                       g_P[(size_t)(2 * r + 1) * NPACK + c]);
}

// xj = (hL - iI)@Qsrc ; Y = XJ = xj ; also write Bbf. Pair of node rows per thread.
__global__ void xj_kernel(const float* __restrict__ hp,
                          const float* __restrict__ Qsrc, int ldq) {
    const int i = blockIdx.x * 256 + threadIdx.x;   // over 1536*256
    const int r = i >> 8;          // pair row
    const int c = i & 255;         // complex col
    const int n0 = 2 * r, n1 = 2 * r + 1;
    const float h = *hp;
    const size_t P = (size_t)NN * FB;
    const size_t i0r = (size_t)n0 * FB + c, i0i = i0r + 256;
    const size_t i1r = (size_t)n1 * FB + c, i1i = i1r + 256;
    const float GR0 = g_G[i0r] + g_G[i0r + P] + g_G[i0r + 2 * P];
    const float GI0 = g_G[i0i] + g_G[i0i + P] + g_G[i0i + 2 * P];
    const float GR1 = g_G[i1r] + g_G[i1r + P] + g_G[i1r + 2 * P];
    const float GI1 = g_G[i1i] + g_G[i1i + P] + g_G[i1i + 2 * P];
    const float q0r = Qsrc[(size_t)n0 * ldq + c], q0i = Qsrc[(size_t)n0 * ldq + c + 256];
    const float q1r = Qsrc[(size_t)n1 * ldq + c], q1i = Qsrc[(size_t)n1 * ldq + c + 256];
    const float x0r = h * q0r - h * GR0 + q0i;
    const float x0i = h * q0i - h * GI0 - q0r;
    const float x1r = h * q1r - h * GR1 + q1i;
    const float x1i = h * q1i - h * GI1 - q1r;
    g_XJ[i0r] = x0r; g_XJ[i0i] = x0i; g_XJ[i1r] = x1r; g_XJ[i1i] = x1i;
    g_Y[i0r] = x0r;  g_Y[i0i] = x0i;  g_Y[i1r] = x1r;  g_Y[i1i] = x1i;
    g_Bbf[(size_t)r * FB + c]       = packbf(x0r, x1r);
    g_Bbf[(size_t)r * FB + c + 256] = packbf(x0i, x1i);
}

__global__ void jacobi_kernel(const float* __restrict__ hp,
                              const float* __restrict__ dr, const float* __restrict__ di) {
    const int i = blockIdx.x * 256 + threadIdx.x;
    const int r = i >> 8;
    const int c = i & 255;
    const int n0 = 2 * r, n1 = 2 * r + 1;
    const float h = *hp;
    const size_t P = (size_t)NN * FB;
    const size_t i0r = (size_t)n0 * FB + c, i0i = i0r + 256;
    const size_t i1r = (size_t)n1 * FB + c, i1i = i1r + 256;
    const float GR0 = g_G[i0r] + g_G[i0r + P] + g_G[i0r + 2 * P];
    const float GI0 = g_G[i0i] + g_G[i0i + P] + g_G[i0i + 2 * P];
    const float GR1 = g_G[i1r] + g_G[i1r + P] + g_G[i1r + 2 * P];
    const float GI1 = g_G[i1i] + g_G[i1i + P] + g_G[i1i + 2 * P];
    const float y0r = g_Y[i0r], y0i = g_Y[i0i];
    const float y1r = g_Y[i1r], y1i = g_Y[i1i];
    const float r0r = g_XJ[i0r] - (h * y0r - h * GR0 - y0i);
    const float r0i = g_XJ[i0i] - (h * y0i - h * GI0 + y0r);
    const float r1r = g_XJ[i1r] - (h * y1r - h * GR1 - y1i);
    const float r1i = g_XJ[i1i] - (h * y1i - h * GI1 + y1r);
    const float d0r = dr[n0], d0i = di[n0];
    const float d1r = dr[n1], d1i = di[n1];
    const float ny0r = y0r + d0r * r0r - d0i * r0i;
    const float ny0i = y0i + d0r * r0i + d0i * r0r;
    const float ny1r = y1r + d1r * r1r - d1i * r1i;
    const float ny1i = y1i + d1r * r1i + d1i * r1r;
    g_Y[i0r] = ny0r; g_Y[i0i] = ny0i; g_Y[i1r] = ny1r; g_Y[i1i] = ny1i;
    g_Bbf[(size_t)r * FB + c]       = packbf(ny0r, ny1r);
    g_Bbf[(size_t)r * FB + c + 256] = packbf(ny0i, ny1i);
}

// Q = P1 + Y (fp32) ; Bbf = bf16 pairs of Q
__global__ void formQ_kernel() {
    const int i = blockIdx.x * 256 + threadIdx.x;   // over 1536*512
    const int r = i >> 9;
    const int c = i & 511;
    const int n0 = 2 * r, n1 = 2 * r + 1;
    const float q0 = g_P[(size_t)n0 * NPACK + 512 + c] + g_Y[(size_t)n0 * FB + c];
    const float q1 = g_P[(size_t)n1 * NPACK + 512 + c] + g_Y[(size_t)n1 * FB + c];
    g_Q[(size_t)n0 * FB + c] = q0;
    g_Q[(size_t)n1 * FB + c] = q1;
    g_Bbf[(size_t)r * FB + c] = packbf(q0, q1);
}

// out = relu(out0 + 2*Re(Y)) ; out0 = g_P[:, 1024:1280]
__global__ void relu_kernel(float* __restrict__ out) {
    const int i = blockIdx.x * blockDim.x + threadIdx.x;
    const size_t r = i >> 8;
    const size_t c = i & 255;
    const float v = g_P[r * NPACK + 1024 + c] + 2.f * g_Y[r * FB + c];
    out[i] = v > 0.f ? v : 0.f;
}

// ---------------- orchestration --------------------------------------------------
#define SMEM_BIG (3 * 17152)

static void applyK(const uint32_t* adjp, const float* hp, const float* dr, const float* di,
                   const float* Qsrc, int ldq, uint32_t* Bbf, float* G) {
    const dim3 gridBig(4, 24, 3);
    gemm_big<<<gridBig, 256, SMEM_BIG>>>(adjp, Bbf, G, (size_t)NN * FB);
    xj_kernel<<<1536, 256>>>(hp, Qsrc, ldq);
    for (int it = 0; it < 3; it++) {
        gemm_big<<<gridBig, 256, SMEM_BIG>>>(adjp, Bbf, G, (size_t)NN * FB);
        jacobi_kernel<<<1536, 256>>>(hp, dr, di);
    }
}

extern "C" void kernel_launch(void* const* d_in, const int* in_sizes, int n_in,
                              void* d_out, int out_size) {
    const float* x   = (const float*)d_in[0];
    const float* adj = (const float*)d_in[1];
    const float* hp  = (const float*)d_in[2];
    const float* w0  = (const float*)d_in[3];
    const float* wr  = (const float*)d_in[4];
    const float* wi  = (const float*)d_in[5];
    float* out = (float*)d_out;

    float *Pp, *WALL, *Q, *Y, *G, *dr, *di;
    uint32_t *adjp, *Bbf;
    cudaGetSymbolAddress((void**)&Pp, g_P);
    cudaGetSymbolAddress((void**)&WALL, g_WALL);
    cudaGetSymbolAddress((void**)&Q, g_Q);
    cudaGetSymbolAddress((void**)&Y, g_Y);
    cudaGetSymbolAddress((void**)&G, g_G);
    cudaGetSymbolAddress((void**)&dr, g_dr);
    cudaGetSymbolAddress((void**)&di, g_di);
    cudaGetSymbolAddress((void**)&adjp, g_adjp);
    cudaGetSymbolAddress((void**)&Bbf, g_Bbf);

    cudaFuncSetAttribute(gemm_big, cudaFuncAttributeMaxDynamicSharedMemorySize, SMEM_BIG);

    rowsum_kernel<<<NN, 256>>>(adj, hp, dr, di);
    packW_kernel<<<(FIN * NPACK) / 256, 256>>>(w0, wr, wi);
    packAdj_kernel<<<dim3(192, 24), 256>>>(adj);

    // P = x @ WALL : [3072, 1280] = [P2 | P1 | out0] (fp32-grade)
    gemm_split<<<dim3(NPACK / 128, NN / 128), 256>>>(x, FIN, WALL, NPACK, Pp, NPACK, FIN);

    // Bbf = bf16(P2)
    packP2_kernel<<<(1536 * 512) / 256, 256>>>();

    // Y = K @ P2
    applyK(adjp, hp, dr, di, Pp, NPACK, Bbf, G);

    // Q = P1 + Y ; Bbf = bf16(Q)
    formQ_kernel<<<(1536 * 512) / 256, 256>>>();

    // Y = K @ Q  (= csum)
    applyK(adjp, hp, dr, di, Q, FB, Bbf, G);

    // out = relu(out0 + 2*Re(csum))
    relu_kernel<<<(NN * FOUT) / 256, 256>>>(out);
}

// round 8
// speedup vs baseline: 2.1398x; 1.1294x over previous
#include <cuda_runtime.h>
#include <cstdint>
#include <cstddef>

#define NN 3072
#define FB 512     // working block width (256 complex -> 512 real cols)
#define FOUT 256
#define FIN 512
#define NPACK 1280 // [wr1|wi1 | wr0|wi0 | w0]

// ---------------- scratch (device globals) -------------------------------------
__device__ __align__(1024) uint32_t g_adjp[(size_t)NN * NN / 2]; // bf16 fragment-tiled adj
__device__ __align__(1024) uint32_t g_Bbf[(NN / 2) * FB];        // bf16x2 interleaved B operand
__device__ __align__(1024) uint32_t g_xh[(size_t)NN * FIN / 2];  // x fragment-tiled bf16 hi
__device__ __align__(1024) uint32_t g_xl[(size_t)NN * FIN / 2];  // x fragment-tiled bf16 lo
__device__ __align__(1024) uint32_t g_wh[(FIN / 2) * NPACK];     // WALL pair-rows bf16 hi
__device__ __align__(1024) uint32_t g_wl[(FIN / 2) * NPACK];     // WALL pair-rows bf16 lo
__device__ __align__(128) float g_P[NN * NPACK];                 // packed projections
__device__ __align__(128) float g_WALL[FIN * NPACK];
__device__ __align__(128) float g_Q[NN * FB];
__device__ __align__(128) float g_Y[NN * FB];
__device__ __align__(128) float g_XJ[NN * FB];
__device__ __align__(128) float g_G[3 * NN * FB];                // split-K partials
__device__ __align__(128) float g_dr[NN];
__device__ __align__(128) float g_di[NN];

// ---------------- helpers -------------------------------------------------------
__device__ __forceinline__ uint32_t packbf(float lo, float hi) {
    uint32_t d;
    asm("cvt.rn.bf16x2.f32 %0, %1, %2;" : "=r"(d) : "f"(hi), "f"(lo));
    return d;
}
__device__ __forceinline__ uint32_t packres(float lo, float hi, uint32_t h) {
    const float hl = __uint_as_float(h << 16);
    const float hh = __uint_as_float(h & 0xFFFF0000u);
    return packbf(lo - hl, hi - hh);
}
__device__ __forceinline__ uint32_t smem_u32(const void* p) {
    uint32_t a;
    asm("{ .reg .u64 t; cvta.to.shared.u64 t, %1; cvt.u32.u64 %0, t; }" : "=r"(a) : "l"(p));
    return a;
}
__device__ __forceinline__ void cpasync16(uint32_t dst, const void* src) {
    asm volatile("cp.async.cg.shared.global [%0], [%1], 16;" :: "r"(dst), "l"(src) : "memory");
}
__device__ __forceinline__ void mma16(float c[4],
                                      uint32_t a0, uint32_t a1, uint32_t a2, uint32_t a3,
                                      uint32_t b0, uint32_t b1) {
    asm volatile(
        "mma.sync.aligned.m16n8k16.row.col.f32.bf16.bf16.f32 "
        "{%0,%1,%2,%3}, {%4,%5,%6,%7}, {%8,%9}, {%0,%1,%2,%3};"
        : "+f"(c[0]), "+f"(c[1]), "+f"(c[2]), "+f"(c[3])
        : "r"(a0), "r"(a1), "r"(a2), "r"(a3), "r"(b0), "r"(b1));
}

// ================= unified pipelined GEMM ========================================
// C[z][m][n] = sum_k A[m][k]*B[k][n], A fragment-tiled bf16 (hi[,lo]),
// B interleaved bf16x2 pair-rows (hi[,lo]). 128x128 CTA, 256 thr, cp.async x3.
// SPLIT: 3 mma passes (Ah·Bh + Ah·Bl + Al·Bh) for fp32-grade output.
// Stage layout (u32): Ah[2112] [Al 2112] Bh[16*136] [Bl 16*136]
template <bool SPLIT>
__global__ void __launch_bounds__(256, 2)
gemm_pipe(const uint32_t* __restrict__ Ah, const uint32_t* __restrict__ Al,
          const uint32_t* __restrict__ Bh, const uint32_t* __restrict__ Bl,
          float* __restrict__ C, int ldc, int ldb, int aTiles,
          int nStages, size_t cPlane) {
    constexpr int AU = 2112;                       // padded A region per array (u32)
    constexpr int BOFF = SPLIT ? 4224 : 2112;      // B hi offset (u32)
    constexpr int BU = 16 * 136;
    constexpr int STAGE = BOFF + (SPLIT ? 2 : 1) * BU;   // u32

    extern __shared__ __align__(16) uint32_t sm[];
    const uint32_t smb = smem_u32(sm);

    const int tid  = threadIdx.x;
    const int lane = tid & 31;
    const int warp = tid >> 5;
    const int wrow = warp >> 2;
    const int wcol = warp & 3;
    const int g    = lane >> 2;
    const int t    = lane & 3;
    const int bMt  = blockIdx.y;
    const int bN   = blockIdx.x * 128;
    const int kt0  = blockIdx.z * (nStages * 2);

    float acc[4][4][4];
#pragma unroll
    for (int i = 0; i < 4; i++)
#pragma unroll
        for (int j = 0; j < 4; j++)
#pragma unroll
            for (int k = 0; k < 4; k++) acc[i][j][k] = 0.f;

    auto issueStage = [&](int st, int s) {
        const uint32_t stb = smb + st * (STAGE * 4);
        const int kt16 = kt0 + s * 2;
        const size_t atile = ((size_t)bMt * aTiles + kt16) * 1024;
#pragma unroll
        for (int i = 0; i < 2; i++) {
            const int c = tid + i * 256;
            const int j = c >> 8, w = c & 255;
            const uint32_t off = (uint32_t)(j * 1056 + (w >> 6) * 264 + (w & 63) * 4) * 4;
            cpasync16(stb + off, Ah + atile + c * 4);
            if (SPLIT) cpasync16(stb + AU * 4 + off, Al + atile + c * 4);
        }
        const size_t brow = (size_t)kt16 * 8 * ldb + bN;
#pragma unroll
        for (int i = 0; i < 2; i++) {
            const int c = tid + i * 256;
            const int row = c >> 5, c4 = (c & 31) * 4;
            const uint32_t off = (uint32_t)(row * 136 + c4) * 4;
            cpasync16(stb + BOFF * 4 + off, Bh + brow + (size_t)row * ldb + c4);
            if (SPLIT) cpasync16(stb + (BOFF + BU) * 4 + off,
                                 Bl + brow + (size_t)row * ldb + c4);
        }
        asm volatile("cp.async.commit_group;" ::: "memory");
    };

    issueStage(0, 0);
    issueStage(1, 1);

    for (int s = 0; s < nStages; s++) {
        const int st = s % 3;
        if (s + 1 < nStages) asm volatile("cp.async.wait_group 1;" ::: "memory");
        else                 asm volatile("cp.async.wait_group 0;" ::: "memory");
        __syncthreads();
        if (s + 2 < nStages) issueStage((s + 2) % 3, s + 2);

        const uint32_t* Sb = sm + st * STAGE;
        const uint32_t* Abase = Sb + t * 264;
        const uint32_t* Bbase = Sb + BOFF;
#pragma unroll
        for (int ks = 0; ks < 2; ks++) {
            uint4 afh[4];
            uint32_t bfh[4][2];
#pragma unroll
            for (int mti = 0; mti < 4; mti++)
                afh[mti] = *(const uint4*)(Abase + ks * 1056 + ((wrow * 4 + mti) * 8 + g) * 4);
#pragma unroll
            for (int nt = 0; nt < 4; nt++) {
                const int n0 = wcol * 32 + nt * 8 + g;
                bfh[nt][0] = Bbase[(ks * 8 + t) * 136 + n0];
                bfh[nt][1] = Bbase[(ks * 8 + t + 4) * 136 + n0];
            }
            if (!SPLIT) {
#pragma unroll
                for (int mti = 0; mti < 4; mti++)
#pragma unroll
                    for (int nt = 0; nt < 4; nt++)
                        mma16(acc[mti][nt], afh[mti].x, afh[mti].y, afh[mti].z, afh[mti].w,
                              bfh[nt][0], bfh[nt][1]);
            } else {
                uint4 afl[4];
                uint32_t bfl[4][2];
#pragma unroll
                for (int mti = 0; mti < 4; mti++)
                    afl[mti] = *(const uint4*)(Abase + AU + ks * 1056 +
                                               ((wrow * 4 + mti) * 8 + g) * 4);
#pragma unroll
                for (int nt = 0; nt < 4; nt++) {
                    const int n0 = wcol * 32 + nt * 8 + g;
                    bfl[nt][0] = Bbase[BU + (ks * 8 + t) * 136 + n0];
                    bfl[nt][1] = Bbase[BU + (ks * 8 + t + 4) * 136 + n0];
                }
#pragma unroll
                for (int mti = 0; mti < 4; mti++)
#pragma unroll
                    for (int nt = 0; nt < 4; nt++) {
                        mma16(acc[mti][nt], afh[mti].x, afh[mti].y, afh[mti].z, afh[mti].w,
                              bfl[nt][0], bfl[nt][1]);
                        mma16(acc[mti][nt], afl[mti].x, afl[mti].y, afl[mti].z, afl[mti].w,
                              bfh[nt][0], bfh[nt][1]);
                        mma16(acc[mti][nt], afh[mti].x, afh[mti].y, afh[mti].z, afh[mti].w,
                              bfh[nt][0], bfh[nt][1]);
                    }
            }
        }
        __syncthreads();
    }

    float* Ct = C + blockIdx.z * cPlane;
#pragma unroll
    for (int mti = 0; mti < 4; mti++) {
        const int row = bMt * 128 + wrow * 64 + mti * 16 + g;
#pragma unroll
        for (int nt = 0; nt < 4; nt++) {
            const int col = bN + wcol * 32 + nt * 8 + 2 * t;
            float* p = Ct + (size_t)row * ldc + col;
            p[0]                   = acc[mti][nt][0];
            p[1]                   = acc[mti][nt][1];
            p[(size_t)8 * ldc]     = acc[mti][nt][2];
            p[(size_t)8 * ldc + 1] = acc[mti][nt][3];
        }
    }
}

// ---------------- pack / elementwise kernels -------------------------------------

// src fp32 [rows x K] -> fragment-tiled bf16 hi (dsth) and optional lo (dstl).
__device__ __forceinline__ void packFragRow(const float* __restrict__ src, int K,
                                            uint32_t* __restrict__ dsth,
                                            uint32_t* __restrict__ dstl,
                                            int ktiles, int kt, int mt, int tp) {
    const int mloc = tp >> 1, half = tp & 1;
    const float* s = src + (size_t)(mt * 128 + mloc) * K + kt * 16 + half * 8;
    const float4 v0 = *(const float4*)s;
    const float4 v1 = *(const float4*)(s + 4);
    const float v[8] = {v0.x, v0.y, v0.z, v0.w, v1.x, v1.y, v1.z, v1.w};
    const int mg   = (mloc & 7) | ((mloc >> 4) << 3);
    const int msel = (mloc >> 3) & 1;
    const int reg  = half * 2 + msel;
    const size_t base = ((size_t)mt * ktiles + kt) * 1024 + mg * 4 + reg;
#pragma unroll
    for (int tt = 0; tt < 4; tt++) {
        const uint32_t h = packbf(v[2 * tt], v[2 * tt + 1]);
        dsth[base + tt * 256] = h;
        if (dstl) dstl[base + tt * 256] = packres(v[2 * tt], v[2 * tt + 1], h);
    }
}

__global__ void packAdj_kernel(const float* __restrict__ adj) {
    packFragRow(adj, NN, g_adjp, nullptr, 192, blockIdx.x, blockIdx.y, threadIdx.x);
}
__global__ void packX_kernel(const float* __restrict__ x) {
    packFragRow(x, FIN, g_xh, g_xl, 32, blockIdx.x, blockIdx.y, threadIdx.x);
}

// WALL [512,1280] -> pair-row hi/lo
__global__ void packWpair_kernel() {
    const int i = blockIdx.x * 256 + threadIdx.x;   // over 256*1280
    const int r = i / NPACK;
    const int c = i % NPACK;
    const float v0 = g_WALL[(size_t)(2 * r) * NPACK + c];
    const float v1 = g_WALL[(size_t)(2 * r + 1) * NPACK + c];
    const uint32_t h = packbf(v0, v1);
    g_wh[i] = h;
    g_wl[i] = packres(v0, v1, h);
}

__global__ void rowsum_kernel(const float* __restrict__ adj, const float* __restrict__ hp,
                              float* __restrict__ dr, float* __restrict__ di) {
    __shared__ float sh[256];
    const int row = blockIdx.x;
    const float* a = adj + (size_t)row * NN;
    float s = 0.f;
    for (int c = threadIdx.x; c < NN; c += 256) s += a[c];
    sh[threadIdx.x] = s;
    __syncthreads();
    for (int o = 128; o > 0; o >>= 1) {
        if (threadIdx.x < o) sh[threadIdx.x] += sh[threadIdx.x + o];
        __syncthreads();
    }
    if (threadIdx.x == 0) {
        const float h = *hp;
        const float sv = h * (1.0f - sh[0]);
        const float inv = 1.0f / (sv * sv + 1.0f);
        dr[row] = sv * inv;
        di[row] = -inv;
    }
}

__global__ void packW_kernel(const float* __restrict__ w0,
                             const float* __restrict__ wr, const float* __restrict__ wi) {
    const int i = blockIdx.x * blockDim.x + threadIdx.x;
    const int r = i / NPACK;
    const int c = i % NPACK;
    float v;
    if (c < 256)        v = wr[(size_t)FIN * FOUT + r * FOUT + c];
    else if (c < 512)   v = wi[(size_t)FIN * FOUT + r * FOUT + (c - 256)];
    else if (c < 768)   v = wr[(size_t)r * FOUT + (c - 512)];
    else if (c < 1024)  v = wi[(size_t)r * FOUT + (c - 768)];
    else                v = w0[(size_t)r * FOUT + (c - 1024)];
    g_WALL[i] = v;
}

__global__ void packP2_kernel() {
    const int i = blockIdx.x * 256 + threadIdx.x;   // over 1536*512
    const int r = i >> 9;
    const int c = i & 511;
    g_Bbf[(size_t)r * FB + c] = packbf(g_P[(size_t)(2 * r) * NPACK + c],
                                       g_P[(size_t)(2 * r + 1) * NPACK + c]);
}

__global__ void xj_kernel(const float* __restrict__ hp,
                          const float* __restrict__ Qsrc, int ldq) {
    const int i = blockIdx.x * 256 + threadIdx.x;   // over 1536*256
    const int r = i >> 8;
    const int c = i & 255;
    const int n0 = 2 * r, n1 = 2 * r + 1;
    const float h = *hp;
    const size_t P = (size_t)NN * FB;
    const size_t i0r = (size_t)n0 * FB + c, i0i = i0r + 256;
    const size_t i1r = (size_t)n1 * FB + c, i1i = i1r + 256;
    const float GR0 = g_G[i0r] + g_G[i0r + P] + g_G[i0r + 2 * P];
    const float GI0 = g_G[i0i] + g_G[i0i + P] + g_G[i0i + 2 * P];
    const float GR1 = g_G[i1r] + g_G[i1r + P] + g_G[i1r + 2 * P];
    const float GI1 = g_G[i1i] + g_G[i1i + P] + g_G[i1i + 2 * P];
    const float q0r = Qsrc[(size_t)n0 * ldq + c], q0i = Qsrc[(size_t)n0 * ldq + c + 256];
    const float q1r = Qsrc[(size_t)n1 * ldq + c], q1i = Qsrc[(size_t)n1 * ldq + c + 256];
    const float x0r = h * q0r - h * GR0 + q0i;
    const float x0i = h * q0i - h * GI0 - q0r;
    const float x1r = h * q1r - h * GR1 + q1i;
    const float x1i = h * q1i - h * GI1 - q1r;
    g_XJ[i0r] = x0r; g_XJ[i0i] = x0i; g_XJ[i1r] = x1r; g_XJ[i1i] = x1i;
    g_Y[i0r] = x0r;  g_Y[i0i] = x0i;  g_Y[i1r] = x1r;  g_Y[i1i] = x1i;
    g_Bbf[(size_t)r * FB + c]       = packbf(x0r, x1r);
    g_Bbf[(size_t)r * FB + c + 256] = packbf(x0i, x1i);
}

__global__ void jacobi_kernel(const float* __restrict__ hp,
                              const float* __restrict__ dr, const float* __restrict__ di) {
    const int i = blockIdx.x * 256 + threadIdx.x;
    const int r = i >> 8;
    const int c = i & 255;
    const int n0 = 2 * r, n1 = 2 * r + 1;
    const float h = *hp;
    const size_t P = (size_t)NN * FB;
    const size_t i0r = (size_t)n0 * FB + c, i0i = i0r + 256;
    const size_t i1r = (size_t)n1 * FB + c, i1i = i1r + 256;
    const float GR0 = g_G[i0r] + g_G[i0r + P] + g_G[i0r + 2 * P];
    const float GI0 = g_G[i0i] + g_G[i0i + P] + g_G[i0i + 2 * P];
    const float GR1 = g_G[i1r] + g_G[i1r + P] + g_G[i1r + 2 * P];
    const float GI1 = g_G[i1i] + g_G[i1i + P] + g_G[i1i + 2 * P];
    const float y0r = g_Y[i0r], y0i = g_Y[i0i];
    const float y1r = g_Y[i1r], y1i = g_Y[i1i];
    const float r0r = g_XJ[i0r] - (h * y0r - h * GR0 - y0i);
    const float r0i = g_XJ[i0i] - (h * y0i - h * GI0 + y0r);
    const float r1r = g_XJ[i1r] - (h * y1r - h * GR1 - y1i);
    const float r1i = g_XJ[i1i] - (h * y1i - h * GI1 + y1r);
    const float d0r = dr[n0], d0i = di[n0];
    const float d1r = dr[n1], d1i = di[n1];
    const float ny0r = y0r + d0r * r0r - d0i * r0i;
    const float ny0i = y0i + d0r * r0i + d0i * r0r;
    const float ny1r = y1r + d1r * r1r - d1i * r1i;
    const float ny1i = y1i + d1r * r1i + d1i * r1r;
    g_Y[i0r] = ny0r; g_Y[i0i] = ny0i; g_Y[i1r] = ny1r; g_Y[i1i] = ny1i;
    g_Bbf[(size_t)r * FB + c]       = packbf(ny0r, ny1r);
    g_Bbf[(size_t)r * FB + c + 256] = packbf(ny0i, ny1i);
}

__global__ void formQ_kernel() {
    const int i = blockIdx.x * 256 + threadIdx.x;   // over 1536*512
    const int r = i >> 9;
    const int c = i & 511;
    const int n0 = 2 * r, n1 = 2 * r + 1;
    const float q0 = g_P[(size_t)n0 * NPACK + 512 + c] + g_Y[(size_t)n0 * FB + c];
    const float q1 = g_P[(size_t)n1 * NPACK + 512 + c] + g_Y[(size_t)n1 * FB + c];
    g_Q[(size_t)n0 * FB + c] = q0;
    g_Q[(size_t)n1 * FB + c] = q1;
    g_Bbf[(size_t)r * FB + c] = packbf(q0, q1);
}

__global__ void relu_kernel(float* __restrict__ out) {
    const int i = blockIdx.x * blockDim.x + threadIdx.x;
    const size_t r = i >> 8;
    const size_t c = i & 255;
    const float v = g_P[r * NPACK + 1024 + c] + 2.f * g_Y[r * FB + c];
    out[i] = v > 0.f ? v : 0.f;
}

// ---------------- orchestration --------------------------------------------------
#define SMEM_BIG   (3 * 4288 * 4)
#define SMEM_SPLIT (3 * 8576 * 4)

static void applyK(const uint32_t* adjp, const float* hp, const float* dr, const float* di,
                   const float* Qsrc, int ldq, uint32_t* Bbf, float* G) {
    const dim3 gridBig(4, 24, 3);
    gemm_pipe<false><<<gridBig, 256, SMEM_BIG>>>(adjp, nullptr, Bbf, nullptr,
                                                 G, FB, FB, 192, 32, (size_t)NN * FB);
    xj_kernel<<<1536, 256>>>(hp, Qsrc, ldq);
    for (int it = 0; it < 3; it++) {
        gemm_pipe<false><<<gridBig, 256, SMEM_BIG>>>(adjp, nullptr, Bbf, nullptr,
                                                     G, FB, FB, 192, 32, (size_t)NN * FB);
        jacobi_kernel<<<1536, 256>>>(hp, dr, di);
    }
}

extern "C" void kernel_launch(void* const* d_in, const int* in_sizes, int n_in,
                              void* d_out, int out_size) {
    const float* x   = (const float*)d_in[0];
    const float* adj = (const float*)d_in[1];
    const float* hp  = (const float*)d_in[2];
    const float* w0  = (const float*)d_in[3];
    const float* wr  = (const float*)d_in[4];
    const float* wi  = (const float*)d_in[5];
    float* out = (float*)d_out;

    float *Pp, *Q, *Y, *G, *dr, *di;
    uint32_t *adjp, *Bbf, *xh, *xl, *wh, *wl;
    cudaGetSymbolAddress((void**)&Pp, g_P);
    cudaGetSymbolAddress((void**)&Q, g_Q);
    cudaGetSymbolAddress((void**)&Y, g_Y);
    cudaGetSymbolAddress((void**)&G, g_G);
    cudaGetSymbolAddress((void**)&dr, g_dr);
    cudaGetSymbolAddress((void**)&di, g_di);
    cudaGetSymbolAddress((void**)&adjp, g_adjp);
    cudaGetSymbolAddress((void**)&Bbf, g_Bbf);
    cudaGetSymbolAddress((void**)&xh, g_xh);
    cudaGetSymbolAddress((void**)&xl, g_xl);
    cudaGetSymbolAddress((void**)&wh, g_wh);
    cudaGetSymbolAddress((void**)&wl, g_wl);

    cudaFuncSetAttribute(gemm_pipe<false>, cudaFuncAttributeMaxDynamicSharedMemorySize, SMEM_BIG);
    cudaFuncSetAttribute(gemm_pipe<true>,  cudaFuncAttributeMaxDynamicSharedMemorySize, SMEM_SPLIT);

    rowsum_kernel<<<NN, 256>>>(adj, hp, dr, di);
    packW_kernel<<<(FIN * NPACK) / 256, 256>>>(w0, wr, wi);
    packWpair_kernel<<<(256 * NPACK) / 256, 256>>>();
    packX_kernel<<<dim3(32, 24), 256>>>(x);
    packAdj_kernel<<<dim3(192, 24), 256>>>(adj);

    // P = x @ WALL : [3072, 1280] = [P2 | P1 | out0] (split-bf16, fp32-grade)
    gemm_pipe<true><<<dim3(10, 24, 1), 256, SMEM_SPLIT>>>(xh, xl, wh, wl,
                                                          Pp, NPACK, NPACK, 32, 16, 0);

    // Bbf = bf16(P2)
    packP2_kernel<<<(1536 * 512) / 256, 256>>>();

    // Y = K @ P2
    applyK(adjp, hp, dr, di, Pp, NPACK, Bbf, G);

    // Q = P1 + Y ; Bbf = bf16(Q)
    formQ_kernel<<<(1536 * 512) / 256, 256>>>();

    // Y = K @ Q  (= csum)
    applyK(adjp, hp, dr, di, Q, FB, Bbf, G);

    // out = relu(out0 + 2*Re(csum))
    relu_kernel<<<(NN * FOUT) / 256, 256>>>(out);
}